// round 3
// baseline (speedup 1.0000x reference)
#include <cuda_runtime.h>

#define NB 16384
#define ND 512
#define NK 8192

#define BM 128
#define BN 128
#define BK 16
#define PITCH (BM + 4)   // 132 floats per smem row: conflict-free frag loads, 2-way STS

__device__ float g_enorm[NK];
__device__ float g_znorm[NB];
__device__ int   g_idx[NB];
__device__ float g_lpart[NB / 4];

// ---------- f32x2 helpers (sm_100+/sm_103a packed fp32) ----------
__device__ __forceinline__ unsigned long long splat2(float x) {
    unsigned long long r;
    asm("mov.b64 %0, {%1, %1};" : "=l"(r) : "f"(x));
    return r;
}
__device__ __forceinline__ void ffma2(unsigned long long& d, unsigned long long a, unsigned long long b) {
    asm("fma.rn.f32x2 %0, %1, %2, %0;" : "+l"(d) : "l"(a), "l"(b));
}
__device__ __forceinline__ void unpack2(unsigned long long v, float& lo, float& hi) {
    asm("mov.b64 {%0, %1}, %2;" : "=f"(lo), "=f"(hi) : "l"(v));
}

// ---------- kernel 1: row squared norms (one warp per row) ----------
// DST selects the __device__ global destination *inside device code* —
// passing a __device__ symbol from host gives the host shadow address (R1 bug).
template <int DST>   // 0 -> g_enorm, 1 -> g_znorm
__global__ void norm_kernel(const float* __restrict__ x) {
    int row  = blockIdx.x * 4 + (threadIdx.x >> 5);
    int lane = threadIdx.x & 31;
    const float4* p = reinterpret_cast<const float4*>(x + (size_t)row * ND);
    float s = 0.f;
#pragma unroll
    for (int i = 0; i < 4; ++i) {
        float4 v = p[lane + 32 * i];
        s += v.x * v.x + v.y * v.y + v.z * v.z + v.w * v.w;
    }
#pragma unroll
    for (int o = 16; o > 0; o >>= 1) s += __shfl_xor_sync(0xffffffffu, s, o);
    if (lane == 0) {
        if (DST == 0) g_enorm[row] = s;
        else          g_znorm[row] = s;
    }
}

// ---------- kernel 2: fused distance GEMM + argmin ----------
__global__ __launch_bounds__(256, 1)
void argmin_kernel(const float* __restrict__ z, const float* __restrict__ e,
                   float* __restrict__ out_idx_f) {
    __shared__ float Zs[BK][PITCH];
    __shared__ float Es[BK][PITCH];
    __shared__ float rbest[BM][17];
    __shared__ int   ridx[BM][17];

    const int tid = threadIdx.x;
    const int tx  = tid & 15;    // n direction (8 cols each)
    const int ty  = tid >> 4;    // m direction (8 rows each)
    const int bm0 = blockIdx.x * BM;

    // global->smem transpose slots: 512 float4 per array, 2 per thread
    const int lrow1 = tid >> 2;              // 0..63
    const int lrow2 = lrow1 + 64;            // 64..127
    const int lc    = (tid & 3) * 4;         // d offset within chunk {0,4,8,12}

    float best[8];
    int   bidx[8];
    float zn[8];
#pragma unroll
    for (int i = 0; i < 8; ++i) {
        best[i] = 3.4e38f;
        bidx[i] = 0;
        zn[i]   = g_znorm[bm0 + ty * 8 + i];
    }

    for (int t = 0; t < NK / BN; ++t) {
        const int n0 = t * BN;

        unsigned long long acc[8][4];
#pragma unroll
        for (int i = 0; i < 8; ++i)
#pragma unroll
            for (int j = 0; j < 4; ++j) acc[i][j] = 0ull;

        // preload chunk 0 into registers
        float4 zr0 = *(const float4*)(z + (size_t)(bm0 + lrow1) * ND + lc);
        float4 zr1 = *(const float4*)(z + (size_t)(bm0 + lrow2) * ND + lc);
        float4 er0 = *(const float4*)(e + (size_t)(n0 + lrow1) * ND + lc);
        float4 er1 = *(const float4*)(e + (size_t)(n0 + lrow2) * ND + lc);

        for (int ch = 0; ch < ND / BK; ++ch) {
            __syncthreads();   // previous compute done, smem reusable
            // transpose-store current chunk (d-major, k-major smem)
            Zs[lc + 0][lrow1] = zr0.x; Zs[lc + 1][lrow1] = zr0.y;
            Zs[lc + 2][lrow1] = zr0.z; Zs[lc + 3][lrow1] = zr0.w;
            Zs[lc + 0][lrow2] = zr1.x; Zs[lc + 1][lrow2] = zr1.y;
            Zs[lc + 2][lrow2] = zr1.z; Zs[lc + 3][lrow2] = zr1.w;
            Es[lc + 0][lrow1] = er0.x; Es[lc + 1][lrow1] = er0.y;
            Es[lc + 2][lrow1] = er0.z; Es[lc + 3][lrow1] = er0.w;
            Es[lc + 0][lrow2] = er1.x; Es[lc + 1][lrow2] = er1.y;
            Es[lc + 2][lrow2] = er1.z; Es[lc + 3][lrow2] = er1.w;
            __syncthreads();

            // prefetch next chunk (latency hidden under compute below)
            if (ch + 1 < ND / BK) {
                const int d0 = (ch + 1) * BK;
                zr0 = *(const float4*)(z + (size_t)(bm0 + lrow1) * ND + d0 + lc);
                zr1 = *(const float4*)(z + (size_t)(bm0 + lrow2) * ND + d0 + lc);
                er0 = *(const float4*)(e + (size_t)(n0 + lrow1) * ND + d0 + lc);
                er1 = *(const float4*)(e + (size_t)(n0 + lrow2) * ND + d0 + lc);
            }

#pragma unroll
            for (int dd = 0; dd < BK; ++dd) {
                float4 za = *(const float4*)&Zs[dd][ty * 8];
                float4 zb = *(const float4*)&Zs[dd][ty * 8 + 4];
                ulonglong2 e01 = *(const ulonglong2*)&Es[dd][tx * 8];
                ulonglong2 e23 = *(const ulonglong2*)&Es[dd][tx * 8 + 4];
                float zf[8] = {za.x, za.y, za.z, za.w, zb.x, zb.y, zb.z, zb.w};
#pragma unroll
                for (int mi = 0; mi < 8; ++mi) {
                    unsigned long long a = splat2(zf[mi]);
                    ffma2(acc[mi][0], a, e01.x);
                    ffma2(acc[mi][1], a, e01.y);
                    ffma2(acc[mi][2], a, e23.x);
                    ffma2(acc[mi][3], a, e23.y);
                }
            }
        }

        // per-tile argmin update; score = (||z||^2 - 2 z.e) + ||e||^2 (ref op order)
        float en8[8];
#pragma unroll
        for (int j = 0; j < 8; ++j) en8[j] = g_enorm[n0 + tx * 8 + j];
#pragma unroll
        for (int mi = 0; mi < 8; ++mi) {
#pragma unroll
            for (int nj = 0; nj < 4; ++nj) {
                float dlo, dhi;
                unpack2(acc[mi][nj], dlo, dhi);
                float s0 = (zn[mi] - 2.f * dlo) + en8[2 * nj];
                float s1 = (zn[mi] - 2.f * dhi) + en8[2 * nj + 1];
                int nbase = n0 + tx * 8 + 2 * nj;
                if (s0 < best[mi]) { best[mi] = s0; bidx[mi] = nbase; }
                if (s1 < best[mi]) { best[mi] = s1; bidx[mi] = nbase + 1; }
            }
        }
    }

    // cross-thread reduction: 16 threads (tx) per row
#pragma unroll
    for (int mi = 0; mi < 8; ++mi) {
        rbest[ty * 8 + mi][tx] = best[mi];
        ridx[ty * 8 + mi][tx]  = bidx[mi];
    }
    __syncthreads();
    if (tid < BM) {
        float b = rbest[tid][0];
        int  ix = ridx[tid][0];
#pragma unroll
        for (int q = 1; q < 16; ++q) {
            float v = rbest[tid][q];
            int  vi = ridx[tid][q];
            if (v < b || (v == b && vi < ix)) { b = v; ix = vi; }
        }
        g_idx[bm0 + tid]     = ix;
        out_idx_f[bm0 + tid] = (float)ix;
    }
}

// ---------- kernel 3: gather quantized rows + per-block loss partial ----------
__global__ void gather_loss_kernel(const float* __restrict__ z, const float* __restrict__ e,
                                   float* __restrict__ outq) {
    int row  = blockIdx.x * 4 + (threadIdx.x >> 6);
    int lane = threadIdx.x & 63;
    int idx  = g_idx[row];
    const float4* zp = (const float4*)(z + (size_t)row * ND);
    const float4* ep = (const float4*)(e + (size_t)idx * ND);
    float4*       op = (float4*)(outq + (size_t)row * ND);
    float s = 0.f;
#pragma unroll
    for (int i = 0; i < 2; ++i) {
        float4 a = zp[lane + 64 * i];
        float4 b = ep[lane + 64 * i];
        op[lane + 64 * i] = b;   // quantized_st == quantized numerically
        float dx = a.x - b.x, dy = a.y - b.y, dz = a.z - b.z, dw = a.w - b.w;
        s += dx * dx + dy * dy + dz * dz + dw * dw;
    }
#pragma unroll
    for (int o = 16; o > 0; o >>= 1) s += __shfl_xor_sync(0xffffffffu, s, o);
    __shared__ float ws[8];
    int w = threadIdx.x >> 5, ln = threadIdx.x & 31;
    if (ln == 0) ws[w] = s;
    __syncthreads();
    if (threadIdx.x == 0) {
        float tsum = 0.f;
#pragma unroll
        for (int i = 0; i < 8; ++i) tsum += ws[i];
        g_lpart[blockIdx.x] = tsum;
    }
}

// ---------- kernel 4: deterministic final loss reduction ----------
__global__ void loss_kernel(float* __restrict__ out_loss) {
    __shared__ double red[256];
    double s = 0.0;
    for (int i = threadIdx.x; i < NB / 4; i += 256) s += (double)g_lpart[i];
    red[threadIdx.x] = s;
    __syncthreads();
    for (int o = 128; o > 0; o >>= 1) {
        if (threadIdx.x < o) red[threadIdx.x] += red[threadIdx.x + o];
        __syncthreads();
    }
    if (threadIdx.x == 0)
        out_loss[0] = (float)(0.25 * red[0] / (double)((long long)NB * ND));
}

extern "C" void kernel_launch(void* const* d_in, const int* in_sizes, int n_in,
                              void* d_out, int out_size) {
    const float* z = (const float*)d_in[0];
    const float* e = (const float*)d_in[1];
    float* out      = (float*)d_out;
    float* outq     = out;                        // [NB*ND]
    float* outidx   = out + (size_t)NB * ND;      // [NB]
    float* outloss  = out + (size_t)NB * ND + NB; // [1]

    norm_kernel<0><<<NK / 4, 128>>>(e);   // -> g_enorm (device-side symbol ref)
    norm_kernel<1><<<NB / 4, 128>>>(z);   // -> g_znorm
    argmin_kernel<<<NB / BM, 256>>>(z, e, outidx);
    gather_loss_kernel<<<NB / 4, 256>>>(z, e, outq);
    loss_kernel<<<1, 256>>>(outloss);
}

// round 4
// speedup vs baseline: 1.6598x; 1.6598x over previous
#include <cuda_runtime.h>

#define NB 16384
#define ND 512
#define NK 8192

#define BM 128
#define BN 128
#define BK 16
#define PITCH (BM + 4)   // 132 floats per smem row: conflict-free frag loads, 2-way STS

__device__ float g_enorm[NK];
__device__ float g_znorm[NB];
__device__ int   g_idx[NB];
__device__ float g_lpart[NB / 4];

// ---------- f32x2 helpers (sm_100+/sm_103a packed fp32) ----------
__device__ __forceinline__ unsigned long long splat2(float x) {
    unsigned long long r;
    asm("mov.b64 %0, {%1, %1};" : "=l"(r) : "f"(x));
    return r;
}
__device__ __forceinline__ void ffma2(unsigned long long& d, unsigned long long a, unsigned long long b) {
    asm("fma.rn.f32x2 %0, %1, %2, %0;" : "+l"(d) : "l"(a), "l"(b));
}
__device__ __forceinline__ void unpack2(unsigned long long v, float& lo, float& hi) {
    asm("mov.b64 {%0, %1}, %2;" : "=f"(lo), "=f"(hi) : "l"(v));
}

// ---------- kernel 1: row squared norms (one warp per row) ----------
// DST selects the __device__ global destination *inside device code* —
// passing a __device__ symbol from host gives the host shadow address (R1 bug).
template <int DST>   // 0 -> g_enorm, 1 -> g_znorm
__global__ void norm_kernel(const float* __restrict__ x) {
    int row  = blockIdx.x * 4 + (threadIdx.x >> 5);
    int lane = threadIdx.x & 31;
    const float4* p = reinterpret_cast<const float4*>(x + (size_t)row * ND);
    float s = 0.f;
#pragma unroll
    for (int i = 0; i < 4; ++i) {
        float4 v = p[lane + 32 * i];
        s += v.x * v.x + v.y * v.y + v.z * v.z + v.w * v.w;
    }
#pragma unroll
    for (int o = 16; o > 0; o >>= 1) s += __shfl_xor_sync(0xffffffffu, s, o);
    if (lane == 0) {
        if (DST == 0) g_enorm[row] = s;
        else          g_znorm[row] = s;
    }
}

// ---------- kernel 2: fused distance GEMM + argmin ----------
__global__ __launch_bounds__(256, 1)
void argmin_kernel(const float* __restrict__ z, const float* __restrict__ e,
                   float* __restrict__ out_idx_f) {
    __shared__ float Zs[BK][PITCH];
    __shared__ float Es[BK][PITCH];
    __shared__ float rbest[BM][17];
    __shared__ int   ridx[BM][17];

    const int tid = threadIdx.x;
    const int tx  = tid & 15;    // n direction (8 cols each)
    const int ty  = tid >> 4;    // m direction (8 rows each)
    const int bm0 = blockIdx.x * BM;

    // global->smem transpose slots: 512 float4 per array, 2 per thread
    const int lrow1 = tid >> 2;              // 0..63
    const int lrow2 = lrow1 + 64;            // 64..127
    const int lc    = (tid & 3) * 4;         // d offset within chunk {0,4,8,12}

    float best[8];
    int   bidx[8];
    float zn[8];
#pragma unroll
    for (int i = 0; i < 8; ++i) {
        best[i] = 3.4e38f;
        bidx[i] = 0;
        zn[i]   = g_znorm[bm0 + ty * 8 + i];
    }

    for (int t = 0; t < NK / BN; ++t) {
        const int n0 = t * BN;

        unsigned long long acc[8][4];
#pragma unroll
        for (int i = 0; i < 8; ++i)
#pragma unroll
            for (int j = 0; j < 4; ++j) acc[i][j] = 0ull;

        // preload chunk 0 into registers
        float4 zr0 = *(const float4*)(z + (size_t)(bm0 + lrow1) * ND + lc);
        float4 zr1 = *(const float4*)(z + (size_t)(bm0 + lrow2) * ND + lc);
        float4 er0 = *(const float4*)(e + (size_t)(n0 + lrow1) * ND + lc);
        float4 er1 = *(const float4*)(e + (size_t)(n0 + lrow2) * ND + lc);

        for (int ch = 0; ch < ND / BK; ++ch) {
            __syncthreads();   // previous compute done, smem reusable
            // transpose-store current chunk (d-major, k-major smem)
            Zs[lc + 0][lrow1] = zr0.x; Zs[lc + 1][lrow1] = zr0.y;
            Zs[lc + 2][lrow1] = zr0.z; Zs[lc + 3][lrow1] = zr0.w;
            Zs[lc + 0][lrow2] = zr1.x; Zs[lc + 1][lrow2] = zr1.y;
            Zs[lc + 2][lrow2] = zr1.z; Zs[lc + 3][lrow2] = zr1.w;
            Es[lc + 0][lrow1] = er0.x; Es[lc + 1][lrow1] = er0.y;
            Es[lc + 2][lrow1] = er0.z; Es[lc + 3][lrow1] = er0.w;
            Es[lc + 0][lrow2] = er1.x; Es[lc + 1][lrow2] = er1.y;
            Es[lc + 2][lrow2] = er1.z; Es[lc + 3][lrow2] = er1.w;
            __syncthreads();

            // prefetch next chunk (latency hidden under compute below)
            if (ch + 1 < ND / BK) {
                const int d0 = (ch + 1) * BK;
                zr0 = *(const float4*)(z + (size_t)(bm0 + lrow1) * ND + d0 + lc);
                zr1 = *(const float4*)(z + (size_t)(bm0 + lrow2) * ND + d0 + lc);
                er0 = *(const float4*)(e + (size_t)(n0 + lrow1) * ND + d0 + lc);
                er1 = *(const float4*)(e + (size_t)(n0 + lrow2) * ND + d0 + lc);
            }

#pragma unroll
            for (int dd = 0; dd < BK; ++dd) {
                float4 za = *(const float4*)&Zs[dd][ty * 8];
                float4 zb = *(const float4*)&Zs[dd][ty * 8 + 4];
                ulonglong2 e01 = *(const ulonglong2*)&Es[dd][tx * 8];
                ulonglong2 e23 = *(const ulonglong2*)&Es[dd][tx * 8 + 4];
                float zf[8] = {za.x, za.y, za.z, za.w, zb.x, zb.y, zb.z, zb.w};
#pragma unroll
                for (int mi = 0; mi < 8; ++mi) {
                    unsigned long long a = splat2(zf[mi]);
                    ffma2(acc[mi][0], a, e01.x);
                    ffma2(acc[mi][1], a, e01.y);
                    ffma2(acc[mi][2], a, e23.x);
                    ffma2(acc[mi][3], a, e23.y);
                }
            }
        }

        // per-tile argmin update; score = (||z||^2 - 2 z.e) + ||e||^2 (ref op order)
        float en8[8];
#pragma unroll
        for (int j = 0; j < 8; ++j) en8[j] = g_enorm[n0 + tx * 8 + j];
#pragma unroll
        for (int mi = 0; mi < 8; ++mi) {
#pragma unroll
            for (int nj = 0; nj < 4; ++nj) {
                float dlo, dhi;
                unpack2(acc[mi][nj], dlo, dhi);
                float s0 = (zn[mi] - 2.f * dlo) + en8[2 * nj];
                float s1 = (zn[mi] - 2.f * dhi) + en8[2 * nj + 1];
                int nbase = n0 + tx * 8 + 2 * nj;
                if (s0 < best[mi]) { best[mi] = s0; bidx[mi] = nbase; }
                if (s1 < best[mi]) { best[mi] = s1; bidx[mi] = nbase + 1; }
            }
        }
    }

    // cross-thread reduction: 16 threads (tx) per row
#pragma unroll
    for (int mi = 0; mi < 8; ++mi) {
        rbest[ty * 8 + mi][tx] = best[mi];
        ridx[ty * 8 + mi][tx]  = bidx[mi];
    }
    __syncthreads();
    if (tid < BM) {
        float b = rbest[tid][0];
        int  ix = ridx[tid][0];
#pragma unroll
        for (int q = 1; q < 16; ++q) {
            float v = rbest[tid][q];
            int  vi = ridx[tid][q];
            if (v < b || (v == b && vi < ix)) { b = v; ix = vi; }
        }
        g_idx[bm0 + tid]     = ix;
        out_idx_f[bm0 + tid] = (float)ix;
    }
}

// ---------- kernel 3: gather quantized rows + per-block loss partial ----------
__global__ void gather_loss_kernel(const float* __restrict__ z, const float* __restrict__ e,
                                   float* __restrict__ outq) {
    int row  = blockIdx.x * 4 + (threadIdx.x >> 6);
    int lane = threadIdx.x & 63;
    int idx  = g_idx[row];
    const float4* zp = (const float4*)(z + (size_t)row * ND);
    const float4* ep = (const float4*)(e + (size_t)idx * ND);
    float4*       op = (float4*)(outq + (size_t)row * ND);
    float s = 0.f;
#pragma unroll
    for (int i = 0; i < 2; ++i) {
        float4 a = zp[lane + 64 * i];
        float4 b = ep[lane + 64 * i];
        op[lane + 64 * i] = b;   // quantized_st == quantized numerically
        float dx = a.x - b.x, dy = a.y - b.y, dz = a.z - b.z, dw = a.w - b.w;
        s += dx * dx + dy * dy + dz * dz + dw * dw;
    }
#pragma unroll
    for (int o = 16; o > 0; o >>= 1) s += __shfl_xor_sync(0xffffffffu, s, o);
    __shared__ float ws[8];
    int w = threadIdx.x >> 5, ln = threadIdx.x & 31;
    if (ln == 0) ws[w] = s;
    __syncthreads();
    if (threadIdx.x == 0) {
        float tsum = 0.f;
#pragma unroll
        for (int i = 0; i < 8; ++i) tsum += ws[i];
        g_lpart[blockIdx.x] = tsum;
    }
}

// ---------- kernel 4: deterministic final loss reduction ----------
__global__ void loss_kernel(float* __restrict__ out_loss) {
    __shared__ double red[256];
    double s = 0.0;
    for (int i = threadIdx.x; i < NB / 4; i += 256) s += (double)g_lpart[i];
    red[threadIdx.x] = s;
    __syncthreads();
    for (int o = 128; o > 0; o >>= 1) {
        if (threadIdx.x < o) red[threadIdx.x] += red[threadIdx.x + o];
        __syncthreads();
    }
    if (threadIdx.x == 0)
        out_loss[0] = (float)(0.25 * red[0] / (double)((long long)NB * ND));
}

extern "C" void kernel_launch(void* const* d_in, const int* in_sizes, int n_in,
                              void* d_out, int out_size) {
    const float* z = (const float*)d_in[0];
    const float* e = (const float*)d_in[1];
    float* out      = (float*)d_out;
    float* outq     = out;                        // [NB*ND]
    float* outidx   = out + (size_t)NB * ND;      // [NB]
    float* outloss  = out + (size_t)NB * ND + NB; // [1]

    norm_kernel<0><<<NK / 4, 128>>>(e);   // -> g_enorm (device-side symbol ref)
    norm_kernel<1><<<NB / 4, 128>>>(z);   // -> g_znorm
    argmin_kernel<<<NB / BM, 256>>>(z, e, outidx);
    gather_loss_kernel<<<NB / 4, 256>>>(z, e, outq);
    loss_kernel<<<1, 256>>>(outloss);
}

// round 8
// speedup vs baseline: 6.8216x; 4.1099x over previous
#include <cuda_runtime.h>
#include <cuda_bf16.h>

#define NB 16384
#define ND 512
#define NK 8192
#define BM 64
#define BN 128
#define NT (NK / BN)          // 64 n-tiles
#define KS (ND / 16)          // 32 k-stages per tile
#define TOT (NT * KS)         // 2048 slots
#define CAP 32
#define MARGIN 8.0f
#define APITCH 520            // bf16 elems per A row (1040B) -> conflict-free ldmatrix
#define BPITCH 24             // bf16 elems per B row (48B)   -> conflict-free ldmatrix
#define A_BYTES (BM * APITCH * 2)                 // 66560
#define B_OFF   A_BYTES
#define B_STG   (BN * BPITCH * 2)                 // 6144
#define ZNL_OFF (B_OFF + 2 * B_STG)               // 78848
#define SB_OFF  (ZNL_OFF + BM * 4)
#define SC_OFF  (SB_OFF + BM * 4)
#define CD_OFF  (SC_OFF + BM * 4)
#define SMEM_SZ (CD_OFF + BM * CAP * 4)           // 87808

__device__ float g_enorm[NK];
__device__ float g_znorm[NB];
__device__ int   g_idx[NB];
__device__ float g_lpart[NB / 4];
__device__ __nv_bfloat16 g_zbf[(size_t)NB * ND];
__device__ __nv_bfloat16 g_ebf[(size_t)NK * ND];

__device__ __forceinline__ unsigned sptr(const void* p) {
    unsigned r;
    asm("{ .reg .u64 t; cvta.to.shared.u64 t, %1; cvt.u32.u64 %0, t; }" : "=r"(r) : "l"(p));
    return r;
}
__device__ __forceinline__ void cpa16(unsigned d, const void* s) {
    asm volatile("cp.async.cg.shared.global [%0], [%1], 16;" :: "r"(d), "l"(s));
}
__device__ __forceinline__ void ldm4(unsigned* r, unsigned a) {
    asm volatile("ldmatrix.sync.aligned.m8n8.x4.shared.b16 {%0,%1,%2,%3}, [%4];"
                 : "=r"(r[0]), "=r"(r[1]), "=r"(r[2]), "=r"(r[3]) : "r"(a));
}
__device__ __forceinline__ void mma(float* c, const unsigned* a, unsigned b0, unsigned b1) {
    asm volatile("mma.sync.aligned.m16n8k16.row.col.f32.bf16.bf16.f32 "
                 "{%0,%1,%2,%3}, {%4,%5,%6,%7}, {%8,%9}, {%0,%1,%2,%3};"
                 : "+f"(c[0]), "+f"(c[1]), "+f"(c[2]), "+f"(c[3])
                 : "r"(a[0]), "r"(a[1]), "r"(a[2]), "r"(a[3]), "r"(b0), "r"(b1));
}

// ---- kernel 1: fp32 norms + bf16 convert (warp per row) ----
template <int DST>  // 0: embedding, 1: z
__global__ void prep_kernel(const float* __restrict__ x) {
    int row = blockIdx.x * 4 + (threadIdx.x >> 5), lane = threadIdx.x & 31;
    const float4* p = (const float4*)(x + (size_t)row * ND);
    uint2* bp = (DST == 0 ? (uint2*)g_ebf : (uint2*)g_zbf) + (size_t)row * (ND / 4);
    float s = 0.f;
#pragma unroll
    for (int i = 0; i < 4; ++i) {
        float4 v = p[lane + 32 * i];
        s += v.x * v.x + v.y * v.y + v.z * v.z + v.w * v.w;
        __nv_bfloat162 h0 = __floats2bfloat162_rn(v.x, v.y);
        __nv_bfloat162 h1 = __floats2bfloat162_rn(v.z, v.w);
        uint2 u = { *(unsigned*)&h0, *(unsigned*)&h1 };
        bp[lane + 32 * i] = u;
    }
#pragma unroll
    for (int o = 16; o > 0; o >>= 1) s += __shfl_xor_sync(~0u, s, o);
    if (lane == 0) { if (DST == 0) g_enorm[row] = s; else g_znorm[row] = s; }
}

// ---- kernel 2: bf16 tensor-core filter + exact fp32 rescore ----
__global__ __launch_bounds__(256, 2)
void filter_kernel(const float* __restrict__ zF, const float* __restrict__ eF,
                   float* __restrict__ oidx) {
    extern __shared__ char sm[];
    float* znl  = (float*)(sm + ZNL_OFF);
    int*   sbst = (int*)(sm + SB_OFF);
    int*   scnt = (int*)(sm + SC_OFF);
    int*   cand = (int*)(sm + CD_OFF);
    const int tid = threadIdx.x, wid = tid >> 5, lane = tid & 31;
    const int bm0 = blockIdx.x * BM;
    const int wm0 = (wid >> 2) * 32;     // warp m-origin (0 or 32)
    const int wn0 = (wid & 3) * 32;      // warp n-origin within BN tile
    const int g = lane >> 2, t2 = (lane & 3) * 2;
    const unsigned sA = sptr(sm), sB = sA + B_OFF;

    // A resident: 64 rows x 512 bf16 = 64 x 64 chunks of 16B. Plus B slot 0.
    {
        const char* src = (const char*)g_zbf + (size_t)bm0 * ND * 2;
#pragma unroll
        for (int i = 0; i < 16; ++i) {
            int c = tid + 256 * i, r = c >> 6, o = c & 63;
            cpa16(sA + (unsigned)(r * APITCH + o * 8) * 2, src + (size_t)r * ND * 2 + o * 16);
        }
        int r = tid >> 1, h = tid & 1;   // B: 128 rows x 16 bf16 (2 chunks/row)
        cpa16(sB + (unsigned)(r * BPITCH + h * 8) * 2,
              (const char*)g_ebf + (size_t)r * ND * 2 + h * 16);
        asm volatile("cp.async.commit_group;");
    }
    for (int i = tid; i < BM; i += 256) {
        sbst[i] = 0x7f7fffff; scnt[i] = 0; znl[i] = g_znorm[bm0 + i];
    }

    float acc[2][4][4];
#pragma unroll
    for (int a = 0; a < 2; ++a)
#pragma unroll
        for (int b = 0; b < 4; ++b)
#pragma unroll
            for (int c = 0; c < 4; ++c) acc[a][b][c] = 0.f;

    for (int s = 0; s < TOT; ++s) {
        asm volatile("cp.async.wait_group 0;");
        __syncthreads();
        if (s + 1 < TOT) {                           // prefetch next B stage
            int n0n = ((s + 1) >> 5) * BN, k0n = ((s + 1) & 31) * 16;
            int r = tid >> 1, h = tid & 1;
            unsigned dst = sB + (unsigned)(((s + 1) & 1) * B_STG)
                              + (unsigned)(r * BPITCH + h * 8) * 2;
            cpa16(dst, (const char*)g_ebf + ((size_t)(n0n + r) * ND + k0n + h * 8) * 2);
            asm volatile("cp.async.commit_group;");
        }
        const int ks = s & 31, n0 = (s >> 5) * BN;
        const unsigned bb = sB + (unsigned)((s & 1) * B_STG);
        unsigned a0[4], a1[4], b0[4], b1[4];
        ldm4(a0, sA + (unsigned)((wm0      + (lane & 15)) * APITCH + ks * 16 + (lane >> 4) * 8) * 2);
        ldm4(a1, sA + (unsigned)((wm0 + 16 + (lane & 15)) * APITCH + ks * 16 + (lane >> 4) * 8) * 2);
        ldm4(b0, bb + (unsigned)((wn0      + (lane & 15)) * BPITCH + (lane >> 4) * 8) * 2);
        ldm4(b1, bb + (unsigned)((wn0 + 16 + (lane & 15)) * BPITCH + (lane >> 4) * 8) * 2);
        // b fragment pairing: same n-octet, both k-halves: (b[0],b[2]) and (b[1],b[3])
        mma(acc[0][0], a0, b0[0], b0[2]); mma(acc[0][1], a0, b0[1], b0[3]);
        mma(acc[0][2], a0, b1[0], b1[2]); mma(acc[0][3], a0, b1[1], b1[3]);
        mma(acc[1][0], a1, b0[0], b0[2]); mma(acc[1][1], a1, b0[1], b0[3]);
        mma(acc[1][2], a1, b1[0], b1[2]); mma(acc[1][3], a1, b1[1], b1[3]);

        if (ks == 31) {   // tile epilogue: d = zn - 2*dot + en
            float d[2][4][4];
#pragma unroll
            for (int mi = 0; mi < 2; ++mi) {
                int r0 = wm0 + mi * 16 + g;
                float zA = znl[r0], zB = znl[r0 + 8];
                float m0 = 3.4e38f, m1 = 3.4e38f;
#pragma unroll
                for (int ni = 0; ni < 4; ++ni) {
                    int c = n0 + wn0 + ni * 8 + t2;
                    float e0 = __ldg(&g_enorm[c]), e1 = __ldg(&g_enorm[c + 1]);
                    d[mi][ni][0] = (zA - 2.f * acc[mi][ni][0]) + e0;
                    d[mi][ni][1] = (zA - 2.f * acc[mi][ni][1]) + e1;
                    d[mi][ni][2] = (zB - 2.f * acc[mi][ni][2]) + e0;
                    d[mi][ni][3] = (zB - 2.f * acc[mi][ni][3]) + e1;
                    m0 = fminf(m0, fminf(d[mi][ni][0], d[mi][ni][1]));
                    m1 = fminf(m1, fminf(d[mi][ni][2], d[mi][ni][3]));
                    acc[mi][ni][0] = acc[mi][ni][1] = acc[mi][ni][2] = acc[mi][ni][3] = 0.f;
                }
                atomicMin(&sbst[r0],     __float_as_int(m0));  // positive floats: int order ok
                atomicMin(&sbst[r0 + 8], __float_as_int(m1));
            }
            __syncthreads();
            // runmin >= d(j*)-2.6 and d~(j*) <= d(j*)+2.6  =>  d~(j*)-runmin <= 5.2 < MARGIN:
            // the true argmin is always collected; everything >= runmin+MARGIN is provably not it.
#pragma unroll
            for (int mi = 0; mi < 2; ++mi) {
                int r0 = wm0 + mi * 16 + g;
                float t0 = __int_as_float(sbst[r0]) + MARGIN;
                float t1 = __int_as_float(sbst[r0 + 8]) + MARGIN;
#pragma unroll
                for (int ni = 0; ni < 4; ++ni) {
                    int c = n0 + wn0 + ni * 8 + t2;
#pragma unroll
                    for (int q = 0; q < 4; ++q) {
                        int  rr  = (q < 2) ? r0 : r0 + 8;
                        float th = (q < 2) ? t0 : t1;
                        if (d[mi][ni][q] < th) {
                            int sl = atomicAdd(&scnt[rr], 1);
                            if (sl < CAP) cand[rr * CAP + sl] = c + (q & 1);
                        }
                    }
                }
            }
            __syncthreads();
        }
    }

    // ---- exact fp32 rescore (one warp per row, 8 rows per warp) ----
    for (int rr = 0; rr < 8; ++rr) {
        const int lr = wid * 8 + rr, row = bm0 + lr;
        const float4* zp = (const float4*)(zF + (size_t)row * ND);
        float4 zr[4];
#pragma unroll
        for (int i = 0; i < 4; ++i) zr[i] = zp[lane + 32 * i];
        const float zn = g_znorm[row];
        float best = 3.4e38f; int bix = 0;
        const int cnt = scnt[lr];
        const bool ovf = cnt > CAP;          // safety fallback: full exact scan
        const int nc = ovf ? NK : cnt;
        for (int k = 0; k < nc; ++k) {
            int ci = ovf ? k : cand[lr * CAP + k];
            const float4* ep = (const float4*)(eF + (size_t)ci * ND);
            float sdot = 0.f;
#pragma unroll
            for (int i = 0; i < 4; ++i) {
                float4 v = ep[lane + 32 * i];
                sdot += zr[i].x * v.x + zr[i].y * v.y + zr[i].z * v.z + zr[i].w * v.w;
            }
#pragma unroll
            for (int o = 16; o > 0; o >>= 1) sdot += __shfl_xor_sync(~0u, sdot, o);
            float dv = (zn - 2.f * sdot) + g_enorm[ci];
            if (dv < best || (dv == best && ci < bix)) { best = dv; bix = ci; }
        }
        if (lane == 0) { g_idx[row] = bix; oidx[row] = (float)bix; }
    }
}

// ---- kernel 3: gather + loss partials ----
__global__ void gather_loss_kernel(const float* __restrict__ z, const float* __restrict__ e,
                                   float* __restrict__ outq) {
    int row = blockIdx.x * 4 + (threadIdx.x >> 6), lane = threadIdx.x & 63;
    int idx = g_idx[row];
    const float4* zp = (const float4*)(z + (size_t)row * ND);
    const float4* ep = (const float4*)(e + (size_t)idx * ND);
    float4* op = (float4*)(outq + (size_t)row * ND);
    float s = 0.f;
#pragma unroll
    for (int i = 0; i < 2; ++i) {
        float4 a = zp[lane + 64 * i], b = ep[lane + 64 * i];
        op[lane + 64 * i] = b;
        float dx = a.x - b.x, dy = a.y - b.y, dz = a.z - b.z, dw = a.w - b.w;
        s += dx * dx + dy * dy + dz * dz + dw * dw;
    }
#pragma unroll
    for (int o = 16; o > 0; o >>= 1) s += __shfl_xor_sync(~0u, s, o);
    __shared__ float ws[8];
    if ((threadIdx.x & 31) == 0) ws[threadIdx.x >> 5] = s;
    __syncthreads();
    if (threadIdx.x == 0) {
        float ts = 0.f;
#pragma unroll
        for (int i = 0; i < 8; ++i) ts += ws[i];
        g_lpart[blockIdx.x] = ts;
    }
}

// ---- kernel 4: deterministic final loss ----
__global__ void loss_kernel(float* __restrict__ out_loss) {
    __shared__ double red[256];
    double s = 0.0;
    for (int i = threadIdx.x; i < NB / 4; i += 256) s += (double)g_lpart[i];
    red[threadIdx.x] = s;
    __syncthreads();
    for (int o = 128; o > 0; o >>= 1) {
        if (threadIdx.x < o) red[threadIdx.x] += red[threadIdx.x + o];
        __syncthreads();
    }
    if (threadIdx.x == 0)
        out_loss[0] = (float)(0.25 * red[0] / (double)((long long)NB * ND));
}

extern "C" void kernel_launch(void* const* d_in, const int* in_sizes, int n_in,
                              void* d_out, int out_size) {
    const float* z = (const float*)d_in[0];
    const float* e = (const float*)d_in[1];
    float* out     = (float*)d_out;
    float* outidx  = out + (size_t)NB * ND;
    float* outloss = out + (size_t)NB * ND + NB;

    // idempotent, not a stream op: safe under graph capture, no static guard needed
    cudaFuncSetAttribute(filter_kernel, cudaFuncAttributeMaxDynamicSharedMemorySize, SMEM_SZ);

    prep_kernel<0><<<NK / 4, 128>>>(e);
    prep_kernel<1><<<NB / 4, 128>>>(z);
    filter_kernel<<<NB / BM, 256, SMEM_SZ>>>(z, e, outidx);
    gather_loss_kernel<<<NB / 4, 256>>>(z, e, out);
    loss_kernel<<<1, 256>>>(outloss);
}

// round 12
// speedup vs baseline: 6.9680x; 1.0214x over previous
#include <cuda_runtime.h>
#include <cuda_bf16.h>

#define NB 16384
#define ND 512
#define NK 8192
#define BM 64
#define BN 128
#define NT (NK / BN)          // 64 n-tiles
#define KSG 8                 // k-stages per tile (k=64 each)
#define NSTG (NT * KSG)       // 512 pipeline stages
#define CAP 32
#define MARGIN 8.0f
#define APITCH 520            // bf16 elems per A row (1040B) -> conflict-free ldmatrix
#define BPITCH 72             // bf16 elems per B row (144B)  -> conflict-free ldmatrix
#define A_BYTES (BM * APITCH * 2)                 // 66560
#define B_OFF   A_BYTES
#define B_STG   (BN * BPITCH * 2)                 // 18432
#define ZNL_OFF (B_OFF + 2 * B_STG)               // 103424
#define SB_OFF  (ZNL_OFF + BM * 4)
#define SC_OFF  (SB_OFF + BM * 4)
#define CD_OFF  (SC_OFF + BM * 4)
#define SMEM_SZ (CD_OFF + BM * CAP * 4)           // 112384

__device__ float g_enorm[NK];
__device__ float g_znorm[NB];
__device__ int   g_idx[NB];
__device__ float g_lpart[NB / 4];
__device__ __nv_bfloat16 g_zbf[(size_t)NB * ND];
__device__ __nv_bfloat16 g_ebf[(size_t)NK * ND];

__device__ __forceinline__ unsigned sptr(const void* p) {
    unsigned r;
    asm("{ .reg .u64 t; cvta.to.shared.u64 t, %1; cvt.u32.u64 %0, t; }" : "=r"(r) : "l"(p));
    return r;
}
__device__ __forceinline__ void cpa16(unsigned d, const void* s) {
    asm volatile("cp.async.cg.shared.global [%0], [%1], 16;" :: "r"(d), "l"(s));
}
__device__ __forceinline__ void ldm4(unsigned* r, unsigned a) {
    asm volatile("ldmatrix.sync.aligned.m8n8.x4.shared.b16 {%0,%1,%2,%3}, [%4];"
                 : "=r"(r[0]), "=r"(r[1]), "=r"(r[2]), "=r"(r[3]) : "r"(a));
}
__device__ __forceinline__ void mma(float* c, const unsigned* a, unsigned b0, unsigned b1) {
    asm volatile("mma.sync.aligned.m16n8k16.row.col.f32.bf16.bf16.f32 "
                 "{%0,%1,%2,%3}, {%4,%5,%6,%7}, {%8,%9}, {%0,%1,%2,%3};"
                 : "+f"(c[0]), "+f"(c[1]), "+f"(c[2]), "+f"(c[3])
                 : "r"(a[0]), "r"(a[1]), "r"(a[2]), "r"(a[3]), "r"(b0), "r"(b1));
}

// ---- kernel 1: fp32 norms + bf16 convert (warp per row) ----
template <int DST>  // 0: embedding, 1: z
__global__ void prep_kernel(const float* __restrict__ x) {
    int row = blockIdx.x * 4 + (threadIdx.x >> 5), lane = threadIdx.x & 31;
    const float4* p = (const float4*)(x + (size_t)row * ND);
    uint2* bp = (DST == 0 ? (uint2*)g_ebf : (uint2*)g_zbf) + (size_t)row * (ND / 4);
    float s = 0.f;
#pragma unroll
    for (int i = 0; i < 4; ++i) {
        float4 v = p[lane + 32 * i];
        s += v.x * v.x + v.y * v.y + v.z * v.z + v.w * v.w;
        __nv_bfloat162 h0 = __floats2bfloat162_rn(v.x, v.y);
        __nv_bfloat162 h1 = __floats2bfloat162_rn(v.z, v.w);
        uint2 u = { *(unsigned*)&h0, *(unsigned*)&h1 };
        bp[lane + 32 * i] = u;
    }
#pragma unroll
    for (int o = 16; o > 0; o >>= 1) s += __shfl_xor_sync(~0u, s, o);
    if (lane == 0) { if (DST == 0) g_enorm[row] = s; else g_znorm[row] = s; }
}

// stage loader: 128 rows x 64 bf16 (= 8 x 16B chunks/row); 256 threads, 4 chunks each
__device__ __forceinline__ void load_bstage(unsigned bb, int stage, int tid) {
    const int tile = stage >> 3, kb = (stage & 7) * 64;
    const int r = tid >> 1, h = tid & 1;           // 2 threads/row, 4 chunks each
    const char* src = (const char*)g_ebf + (((size_t)(tile * BN + r)) * ND + kb + h * 32) * 2;
    unsigned dst = bb + (unsigned)(r * BPITCH + h * 32) * 2;
#pragma unroll
    for (int j = 0; j < 4; ++j) cpa16(dst + j * 16, src + j * 16);
}

// ---- kernel 2: bf16 tensor-core filter + exact fp32 rescore ----
__global__ __launch_bounds__(256, 2)
void filter_kernel(const float* __restrict__ zF, const float* __restrict__ eF,
                   float* __restrict__ oidx) {
    extern __shared__ char sm[];
    float* znl  = (float*)(sm + ZNL_OFF);
    int*   sbst = (int*)(sm + SB_OFF);
    int*   scnt = (int*)(sm + SC_OFF);
    int*   cand = (int*)(sm + CD_OFF);
    const int tid = threadIdx.x, wid = tid >> 5, lane = tid & 31;
    const int bm0 = blockIdx.x * BM;
    const int wm0 = (wid >> 2) * 32;     // warp m-origin (0 or 32)
    const int wn0 = (wid & 3) * 32;      // warp n-origin within BN tile
    const int g = lane >> 2, t2 = (lane & 3) * 2;
    const unsigned sA = sptr(sm), sB = sA + B_OFF;

    // A resident: 64 rows x 512 bf16 (64 x 16B chunks/row), plus B stage 0
    {
        const char* src = (const char*)g_zbf + (size_t)bm0 * ND * 2;
#pragma unroll
        for (int i = 0; i < 16; ++i) {
            int c = tid + 256 * i, r = c >> 6, o = c & 63;
            cpa16(sA + (unsigned)(r * APITCH + o * 8) * 2, src + (size_t)r * ND * 2 + o * 16);
        }
        load_bstage(sB, 0, tid);
        asm volatile("cp.async.commit_group;");
    }
    for (int i = tid; i < BM; i += 256) {
        sbst[i] = 0x7f7fffff; scnt[i] = 0; znl[i] = g_znorm[bm0 + i];
    }

    float acc[2][4][4];
#pragma unroll
    for (int a = 0; a < 2; ++a)
#pragma unroll
        for (int b = 0; b < 4; ++b)
#pragma unroll
            for (int c = 0; c < 4; ++c) acc[a][b][c] = 0.f;

    for (int s = 0; s < NSTG; ++s) {
        asm volatile("cp.async.wait_group 0;");   // stage s data landed (own group)
        __syncthreads();                           // all warps see it; prev buffer free
        if (s + 1 < NSTG) {                        // prefetch s+1 into other buffer
            load_bstage(sB + (unsigned)(((s + 1) & 1) * B_STG), s + 1, tid);
            asm volatile("cp.async.commit_group;");
        }
        const unsigned bb = sB + (unsigned)((s & 1) * B_STG);
        const int ksg = s & 7, n0 = (s >> 3) * BN;

#pragma unroll
        for (int ku = 0; ku < 4; ++ku) {           // 4 k-steps of 16 per stage
            const int ks = ksg * 4 + ku;
            unsigned a0[4], a1[4], b0[4], b1[4];
            ldm4(a0, sA + (unsigned)((wm0      + (lane & 15)) * APITCH + ks * 16 + (lane >> 4) * 8) * 2);
            ldm4(a1, sA + (unsigned)((wm0 + 16 + (lane & 15)) * APITCH + ks * 16 + (lane >> 4) * 8) * 2);
            ldm4(b0, bb + (unsigned)((wn0      + (lane & 15)) * BPITCH + ku * 16 + (lane >> 4) * 8) * 2);
            ldm4(b1, bb + (unsigned)((wn0 + 16 + (lane & 15)) * BPITCH + ku * 16 + (lane >> 4) * 8) * 2);
            // b pairing: same n-octet, both k-halves: (b[0],b[2]) and (b[1],b[3])
            mma(acc[0][0], a0, b0[0], b0[2]); mma(acc[0][1], a0, b0[1], b0[3]);
            mma(acc[0][2], a0, b1[0], b1[2]); mma(acc[0][3], a0, b1[1], b1[3]);
            mma(acc[1][0], a1, b0[0], b0[2]); mma(acc[1][1], a1, b0[1], b0[3]);
            mma(acc[1][2], a1, b1[0], b1[2]); mma(acc[1][3], a1, b1[1], b1[3]);
        }

        if (ksg == 7) {   // tile epilogue: d = zn - 2*dot + en
            float d[2][4][4];
#pragma unroll
            for (int mi = 0; mi < 2; ++mi) {
                int r0 = wm0 + mi * 16 + g;
                float zA = znl[r0], zB = znl[r0 + 8];
                float m0 = 3.4e38f, m1 = 3.4e38f;
#pragma unroll
                for (int ni = 0; ni < 4; ++ni) {
                    int c = n0 + wn0 + ni * 8 + t2;
                    float e0 = __ldg(&g_enorm[c]), e1 = __ldg(&g_enorm[c + 1]);
                    d[mi][ni][0] = (zA - 2.f * acc[mi][ni][0]) + e0;
                    d[mi][ni][1] = (zA - 2.f * acc[mi][ni][1]) + e1;
                    d[mi][ni][2] = (zB - 2.f * acc[mi][ni][2]) + e0;
                    d[mi][ni][3] = (zB - 2.f * acc[mi][ni][3]) + e1;
                    m0 = fminf(m0, fminf(d[mi][ni][0], d[mi][ni][1]));
                    m1 = fminf(m1, fminf(d[mi][ni][2], d[mi][ni][3]));
                    acc[mi][ni][0] = acc[mi][ni][1] = acc[mi][ni][2] = acc[mi][ni][3] = 0.f;
                }
                atomicMin(&sbst[r0],     __float_as_int(m0));  // positive floats: int order ok
                atomicMin(&sbst[r0 + 8], __float_as_int(m1));
            }
            __syncthreads();
            // runmin >= d(j*)-2.6 and d~(j*) <= d(j*)+2.6  =>  d~(j*)-runmin <= 5.2 < MARGIN:
            // true argmin always collected; anything >= runmin+MARGIN is provably not it.
#pragma unroll
            for (int mi = 0; mi < 2; ++mi) {
                int r0 = wm0 + mi * 16 + g;
                float t0 = __int_as_float(sbst[r0]) + MARGIN;
                float t1 = __int_as_float(sbst[r0 + 8]) + MARGIN;
#pragma unroll
                for (int ni = 0; ni < 4; ++ni) {
                    int c = n0 + wn0 + ni * 8 + t2;
#pragma unroll
                    for (int q = 0; q < 4; ++q) {
                        int  rr  = (q < 2) ? r0 : r0 + 8;
                        float th = (q < 2) ? t0 : t1;
                        if (d[mi][ni][q] < th) {
                            int sl = atomicAdd(&scnt[rr], 1);
                            if (sl < CAP) cand[rr * CAP + sl] = c + (q & 1);
                        }
                    }
                }
            }
        }
    }

    __syncthreads();
    // ---- exact fp32 rescore (one warp per row, 8 rows per warp) ----
    for (int rr = 0; rr < 8; ++rr) {
        const int lr = wid * 8 + rr, row = bm0 + lr;
        const float4* zp = (const float4*)(zF + (size_t)row * ND);
        float4 zr[4];
#pragma unroll
        for (int i = 0; i < 4; ++i) zr[i] = zp[lane + 32 * i];
        const float zn = g_znorm[row];
        float best = 3.4e38f; int bix = 0;
        const int cnt = scnt[lr];
        const bool ovf = cnt > CAP;          // safety fallback: full exact scan
        const int nc = ovf ? NK : cnt;
        for (int k = 0; k < nc; ++k) {
            int ci = ovf ? k : cand[lr * CAP + k];
            const float4* ep = (const float4*)(eF + (size_t)ci * ND);
            float sdot = 0.f;
#pragma unroll
            for (int i = 0; i < 4; ++i) {
                float4 v = ep[lane + 32 * i];
                sdot += zr[i].x * v.x + zr[i].y * v.y + zr[i].z * v.z + zr[i].w * v.w;
            }
#pragma unroll
            for (int o = 16; o > 0; o >>= 1) sdot += __shfl_xor_sync(~0u, sdot, o);
            float dv = (zn - 2.f * sdot) + g_enorm[ci];
            if (dv < best || (dv == best && ci < bix)) { best = dv; bix = ci; }
        }
        if (lane == 0) { g_idx[row] = bix; oidx[row] = (float)bix; }
    }
}

// ---- kernel 3: gather + loss partials ----
__global__ void gather_loss_kernel(const float* __restrict__ z, const float* __restrict__ e,
                                   float* __restrict__ outq) {
    int row = blockIdx.x * 4 + (threadIdx.x >> 6), lane = threadIdx.x & 63;
    int idx = g_idx[row];
    const float4* zp = (const float4*)(z + (size_t)row * ND);
    const float4* ep = (const float4*)(e + (size_t)idx * ND);
    float4* op = (float4*)(outq + (size_t)row * ND);
    float s = 0.f;
#pragma unroll
    for (int i = 0; i < 2; ++i) {
        float4 a = zp[lane + 64 * i], b = ep[lane + 64 * i];
        op[lane + 64 * i] = b;
        float dx = a.x - b.x, dy = a.y - b.y, dz = a.z - b.z, dw = a.w - b.w;
        s += dx * dx + dy * dy + dz * dz + dw * dw;
    }
#pragma unroll
    for (int o = 16; o > 0; o >>= 1) s += __shfl_xor_sync(~0u, s, o);
    __shared__ float ws[8];
    if ((threadIdx.x & 31) == 0) ws[threadIdx.x >> 5] = s;
    __syncthreads();
    if (threadIdx.x == 0) {
        float ts = 0.f;
#pragma unroll
        for (int i = 0; i < 8; ++i) ts += ws[i];
        g_lpart[blockIdx.x] = ts;
    }
}

// ---- kernel 4: deterministic final loss ----
__global__ void loss_kernel(float* __restrict__ out_loss) {
    __shared__ double red[256];
    double s = 0.0;
    for (int i = threadIdx.x; i < NB / 4; i += 256) s += (double)g_lpart[i];
    red[threadIdx.x] = s;
    __syncthreads();
    for (int o = 128; o > 0; o >>= 1) {
        if (threadIdx.x < o) red[threadIdx.x] += red[threadIdx.x + o];
        __syncthreads();
    }
    if (threadIdx.x == 0)
        out_loss[0] = (float)(0.25 * red[0] / (double)((long long)NB * ND));
}

extern "C" void kernel_launch(void* const* d_in, const int* in_sizes, int n_in,
                              void* d_out, int out_size) {
    const float* z = (const float*)d_in[0];
    const float* e = (const float*)d_in[1];
    float* out     = (float*)d_out;
    float* outidx  = out + (size_t)NB * ND;
    float* outloss = out + (size_t)NB * ND + NB;

    cudaFuncSetAttribute(filter_kernel, cudaFuncAttributeMaxDynamicSharedMemorySize, SMEM_SZ);

    prep_kernel<0><<<NK / 4, 128>>>(e);
    prep_kernel<1><<<NB / 4, 128>>>(z);
    filter_kernel<<<NB / BM, 256, SMEM_SZ>>>(z, e, outidx);
    gather_loss_kernel<<<NB / 4, 256>>>(z, e, out);
    loss_kernel<<<1, 256>>>(outloss);
}